// round 11
// baseline (speedup 1.0000x reference)
#include <cuda_runtime.h>
#include <math.h>

#define Bb 16
#define Tt 2048
#define Ii 512
#define Hh 512
#define RR 2048   // 4*H, permuted row order r = 4*j + g
#define NG 4      // independent groups (each owns 4 batches)
#define GC 32     // CTAs per group
#define GB 4      // batches per group
#define ROWS 64   // permuted gate rows per CTA
#define WST 516   // w_s row stride in floats (64x516x4B = 132KB)

// ---------------- persistent device scratch (no runtime allocation) ----------
__device__ float d_WiP[RR * Ii];                 // 4 MB  permuted Wi
__device__ float d_WhP[RR * Hh];                 // 4 MB  permuted Wh
__device__ float d_bsum[RR];                     // bi+bh, permuted
__device__ float d_XG[(size_t)Tt * RR * Bb];     // 268 MB, [t][g][r][b4]
__device__ uint2 d_HX[2][NG * Hh * GB];          // tagged h words (h_bits, tag)

// ---------------- f32x2 helpers ----------------------------------------------
__device__ __forceinline__ unsigned long long ffma2(unsigned long long a,
                                                    unsigned long long b,
                                                    unsigned long long c) {
    unsigned long long d;
    asm("fma.rn.f32x2 %0, %1, %2, %3;" : "=l"(d) : "l"(a), "l"(b), "l"(c));
    return d;
}
__device__ __forceinline__ unsigned long long add2(unsigned long long a,
                                                   unsigned long long b) {
    unsigned long long d;
    asm("add.rn.f32x2 %0, %1, %2;" : "=l"(d) : "l"(a), "l"(b));
    return d;
}
__device__ __forceinline__ unsigned long long packdup(float x) {
    unsigned long long r;
    asm("mov.b64 %0, {%1, %1};" : "=l"(r) : "f"(x));
    return r;
}
__device__ __forceinline__ float2 unpk(unsigned long long v) {
    float2 r;
    asm("mov.b64 {%0, %1}, %2;" : "=f"(r.x), "=f"(r.y) : "l"(v));
    return r;
}

// fresh L2 read of 16B (2 tagged words), never hoisted
__device__ __forceinline__ uint4 ldcg4(const uint4* p) {
    uint4 v;
    asm volatile("ld.global.cg.v4.u32 {%0,%1,%2,%3}, [%4];"
                 : "=r"(v.x), "=r"(v.y), "=r"(v.z), "=r"(v.w)
                 : "l"(p) : "memory");
    return v;
}
// publish one tagged word (data+tag atomic in a single 8B store)
__device__ __forceinline__ void st_word(uint2* p, unsigned hbits, unsigned tag) {
    asm volatile("st.global.cg.v2.u32 [%0], {%1, %2};"
                 :: "l"(p), "r"(hbits), "r"(tag) : "memory");
}

__device__ __forceinline__ float sigmoidf_(float x) {
    return 1.f / (1.f + __expf(-x));
}
__device__ __forceinline__ float tanhf_(float x) {
    float e = __expf(2.f * x);
    return (e - 1.f) / (e + 1.f);
}

// ---------------- phase 0a: permute weights, fuse biases ---------------------
__global__ void permute_kernel(const float* __restrict__ Wi,
                               const float* __restrict__ Wh,
                               const float* __restrict__ bi,
                               const float* __restrict__ bh) {
    int rnew = blockIdx.x;            // 0..2047
    int j = rnew >> 2, g = rnew & 3;
    int rold = g * Hh + j;
    const float4* wi4 = (const float4*)(Wi + (size_t)rold * Ii);
    const float4* wh4 = (const float4*)(Wh + (size_t)rold * Hh);
    float4* wiP4 = (float4*)(d_WiP + (size_t)rnew * Ii);
    float4* whP4 = (float4*)(d_WhP + (size_t)rnew * Hh);
    for (int k = threadIdx.x; k < Ii / 4; k += blockDim.x) wiP4[k] = wi4[k];
    for (int k = threadIdx.x; k < Hh / 4; k += blockDim.x) whP4[k] = wh4[k];
    if (threadIdx.x == 0) d_bsum[rnew] = bi[rold] + bh[rold];
}

// ---------------- phase 0b: init tagged h words ------------------------------
__global__ void init_kernel(const float* __restrict__ h0) {
    int idx = blockIdx.x * blockDim.x + threadIdx.x;   // 0..8191
    if (idx < NG * Hh * GB) {
        int g = idx >> 11;
        int k = (idx & 2047) >> 2;
        int b = idx & 3;
        float h = h0[(size_t)(g * GB + b) * Hh + k];
        d_HX[0][idx] = make_uint2(__float_as_uint(h), 0u);       // tag 0 = h(0)
        d_HX[1][idx] = make_uint2(0u, 0xFFFFFFFFu);              // never matches
    }
}

// ---------------- phase 1: xg[t][g][r][b4] = WiP @ x^T + bsum ----------------
#define BM 128
#define BN 128
#define BK 16
#define LDA 132

__global__ __launch_bounds__(256, 2) void xgemm_kernel(const float* __restrict__ x) {
    __shared__ float As[BK * LDA];
    __shared__ float Bs[BK * LDA];
    const int tid = threadIdx.x;
    const int m0 = blockIdx.y * BM;
    const int n0 = blockIdx.x * BN;
    const int tx = tid & 15, ty = tid >> 4;

    unsigned long long acc[8][4];
#pragma unroll
    for (int i = 0; i < 8; i++)
#pragma unroll
        for (int j = 0; j < 4; j++) acc[i][j] = 0ull;

    for (int k0 = 0; k0 < Ii; k0 += BK) {
#pragma unroll
        for (int q = 0; q < 2; q++) {
            int slot = tid + q * 256;
            int row = slot >> 2;
            int kq4 = slot & 3;
            float4 v = *(const float4*)&d_WiP[(size_t)(m0 + row) * Ii + k0 + kq4 * 4];
            As[(kq4 * 4 + 0) * LDA + row] = v.x;
            As[(kq4 * 4 + 1) * LDA + row] = v.y;
            As[(kq4 * 4 + 2) * LDA + row] = v.z;
            As[(kq4 * 4 + 3) * LDA + row] = v.w;
        }
#pragma unroll
        for (int q = 0; q < 2; q++) {
            int slot = tid + q * 256;
            int nn = slot >> 2;
            int kq4 = slot & 3;
            int n = n0 + nn;
            int t = n >> 4, b = n & 15;
            float4 v = *(const float4*)&x[((size_t)b * Tt + t) * Ii + k0 + kq4 * 4];
            Bs[(kq4 * 4 + 0) * LDA + nn] = v.x;
            Bs[(kq4 * 4 + 1) * LDA + nn] = v.y;
            Bs[(kq4 * 4 + 2) * LDA + nn] = v.z;
            Bs[(kq4 * 4 + 3) * LDA + nn] = v.w;
        }
        __syncthreads();
#pragma unroll
        for (int kk = 0; kk < BK; kk++) {
            float a[8];
            *(float4*)&a[0] = *(const float4*)&As[kk * LDA + ty * 8];
            *(float4*)&a[4] = *(const float4*)&As[kk * LDA + ty * 8 + 4];
            ulonglong2 b01 = *(const ulonglong2*)&Bs[kk * LDA + tx * 8];
            ulonglong2 b23 = *(const ulonglong2*)&Bs[kk * LDA + tx * 8 + 4];
#pragma unroll
            for (int i = 0; i < 8; i++) {
                unsigned long long as = packdup(a[i]);
                acc[i][0] = ffma2(as, b01.x, acc[i][0]);
                acc[i][1] = ffma2(as, b01.y, acc[i][1]);
                acc[i][2] = ffma2(as, b23.x, acc[i][2]);
                acc[i][3] = ffma2(as, b23.y, acc[i][3]);
            }
        }
        __syncthreads();
    }
#pragma unroll
    for (int mm = 0; mm < 8; mm++) {
        int r = m0 + ty * 8 + mm;
        float bias = d_bsum[r];
#pragma unroll
        for (int nq = 0; nq < 2; nq++) {
            int n = n0 + tx * 8 + nq * 4;
            int t = n >> 4, b = n & 15;  // b in {0,4,8,12}: 4 batches of group b>>2
            float2 u0 = unpk(acc[mm][nq * 2 + 0]);
            float2 u1 = unpk(acc[mm][nq * 2 + 1]);
            float4 v;
            v.x = u0.x + bias;
            v.y = u0.y + bias;
            v.z = u1.x + bias;
            v.w = u1.y + bias;
            *(float4*)&d_XG[(size_t)t * (RR * Bb) + (size_t)(b >> 2) * (RR * 4) +
                            (size_t)r * 4] = v;
        }
    }
}

// ---------------- phase 2: persistent recurrent kernel -----------------------
// 4 independent groups x 32 CTAs. CTA (g, cl) owns permuted gate rows
// [64cl, 64cl+64) -> hidden [16cl, 16cl+16), batches [4g, 4g+4).
// Exchange via self-validating (h, tag) words: no flags, no fences.
// h_s is [b][k] so FFMA2 pairs over k: zero packing MOVs in the hot loop.
__global__ __launch_bounds__(256, 1) void lstm_kernel(const float* __restrict__ c0,
                                                      float* __restrict__ out,
                                                      float* __restrict__ hT,
                                                      float* __restrict__ cT) {
    extern __shared__ float sm[];
    float* w_s  = sm;                       // 64 x 516         = 132.1 KB
    float* h_s  = w_s + ROWS * WST;         // 4 x 512 [b][k]   = 8 KB
    float* gred = h_s + GB * Hh;            // 4 x 64 x 4       = 4 KB

    const int tid = threadIdx.x;
    const int g  = blockIdx.x >> 5;
    const int cl = blockIdx.x & 31;
    const int kq = tid >> 6;       // k-split 0..3 (128 k each)
    const int rw = tid & 63;       // local gate row 0..63

    // Wh slice -> SMEM (once)
    {
        const float4* src = (const float4*)(d_WhP + (size_t)(cl * ROWS) * Hh);
        for (int i4 = tid; i4 < ROWS * Hh / 4; i4 += 256) {
            int rr = i4 >> 7;
            int k4 = i4 & 127;
            *(float4*)&w_s[rr * WST + k4 * 4] = src[i4];
        }
    }

    const int jl = tid >> 2, bb = tid & 3;          // tail mapping (tid < 64)
    const int khid  = cl * 16 + jl;
    const int bglob = g * GB + bb;
    float c = 0.f, hlast = 0.f;
    if (tid < 64) c = c0[(size_t)bglob * Hh + khid];
    __syncthreads();

    const float* wrow = w_s + rw * WST + kq * 128;
    const float* hbase = h_s + kq * 128;

    for (int t = 0; t < Tt; t++) {
        // xg for this step (kq==0 threads; fully coalesced 1KB)
        float4 xgv = make_float4(0.f, 0.f, 0.f, 0.f);
        if (kq == 0)
            xgv = __ldcs((const float4*)(d_XG + (size_t)t * (RR * Bb) +
                                         (size_t)g * (RR * 4)) + (cl * ROWS + rw));

        // poll this thread's 64B of tagged words (k = 2*tid, 2*tid+1; all b).
        // Tight spin first (fast path), bounded nanosleep backoff after.
        {
            const uint4* pb = (const uint4*)&d_HX[t & 1][g * 2048] + tid * 4;
            const unsigned tg = (unsigned)t;
            int spins = 0;
            uint4 q0 = ldcg4(pb), q1 = ldcg4(pb + 1),
                  q2 = ldcg4(pb + 2), q3 = ldcg4(pb + 3);
            while ((q0.y != tg) | (q0.w != tg) | (q1.y != tg) | (q1.w != tg) |
                   (q2.y != tg) | (q2.w != tg) | (q3.y != tg) | (q3.w != tg)) {
                if (++spins > 16) __nanosleep(16);
                q0 = ldcg4(pb); q1 = ldcg4(pb + 1);
                q2 = ldcg4(pb + 2); q3 = ldcg4(pb + 3);
            }
            // d_HX words are [k][b]; scatter into h_s [b][k] (k = 2tid, 2tid+1)
            int k0 = 2 * tid;
            *(float2*)&h_s[0 * Hh + k0] =
                make_float2(__uint_as_float(q0.x), __uint_as_float(q2.x));
            *(float2*)&h_s[1 * Hh + k0] =
                make_float2(__uint_as_float(q0.z), __uint_as_float(q2.z));
            *(float2*)&h_s[2 * Hh + k0] =
                make_float2(__uint_as_float(q1.x), __uint_as_float(q3.x));
            *(float2*)&h_s[3 * Hh + k0] =
                make_float2(__uint_as_float(q1.z), __uint_as_float(q3.z));
        }
        __syncthreads();                               // bar1: h_s complete

        // partial gates: row rw, 4 batches, k in [128kq, 128kq+128).
        // k-paired FFMA2: both operands are native u64 pairs, no packing MOVs.
        unsigned long long a0A = 0ull, a0B = 0ull, a1A = 0ull, a1B = 0ull,
                           a2A = 0ull, a2B = 0ull, a3A = 0ull, a3B = 0ull;
#pragma unroll 16
        for (int k4 = 0; k4 < 32; k4++) {
            ulonglong2 w2 = *(const ulonglong2*)(wrow + 4 * k4);
            ulonglong2 h0 = *(const ulonglong2*)(hbase + 0 * Hh + 4 * k4);
            ulonglong2 h1 = *(const ulonglong2*)(hbase + 1 * Hh + 4 * k4);
            ulonglong2 h2 = *(const ulonglong2*)(hbase + 2 * Hh + 4 * k4);
            ulonglong2 h3 = *(const ulonglong2*)(hbase + 3 * Hh + 4 * k4);
            a0A = ffma2(w2.x, h0.x, a0A);  a0B = ffma2(w2.y, h0.y, a0B);
            a1A = ffma2(w2.x, h1.x, a1A);  a1B = ffma2(w2.y, h1.y, a1B);
            a2A = ffma2(w2.x, h2.x, a2A);  a2B = ffma2(w2.y, h2.y, a2B);
            a3A = ffma2(w2.x, h3.x, a3A);  a3B = ffma2(w2.y, h3.y, a3B);
        }
        {
            float2 p0 = unpk(add2(a0A, a0B));
            float2 p1 = unpk(add2(a1A, a1B));
            float2 p2 = unpk(add2(a2A, a2B));
            float2 p3 = unpk(add2(a3A, a3B));
            float4 v;
            v.x = p0.x + p0.y;
            v.y = p1.x + p1.y;
            v.z = p2.x + p2.y;
            v.w = p3.x + p3.y;
            if (kq == 0) {
                v.x += xgv.x; v.y += xgv.y; v.z += xgv.z; v.w += xgv.w;
            }
            *(float4*)&gred[(kq * 64 + rw) * 4] = v;
        }
        __syncthreads();                               // bar2: partials ready

        if (tid < 64) {
            float gate[4];
#pragma unroll
            for (int gt = 0; gt < 4; gt++) {
                int rl = 4 * jl + gt;
                gate[gt] = gred[(0 * 64 + rl) * 4 + bb] +
                           gred[(1 * 64 + rl) * 4 + bb] +
                           gred[(2 * 64 + rl) * 4 + bb] +
                           gred[(3 * 64 + rl) * 4 + bb];
            }
            float ig = sigmoidf_(gate[0]);
            float fg = sigmoidf_(gate[1]);
            float gv = tanhf_(gate[2]);
            float og = sigmoidf_(gate[3]);
            c = fmaf(fg, c, ig * gv);
            float h = og * tanhf_(c);
            hlast = h;
            // publish: data+tag in one 8B word — no fence needed
            st_word(&d_HX[(t + 1) & 1][g * 2048 + khid * 4 + bb],
                    __float_as_uint(h), (unsigned)(t + 1));
            // background drain; nothing orders after this
            out[((size_t)bglob * Tt + t) * Hh + khid] = h;
        }
        // non-tail threads proceed to next poll; gred/h_s reuse is safe:
        // a CTA only passes the next poll after ALL producers (incl. our own
        // tail) published t+1, which happens after the tail read gred(t).
    }

    if (tid < 64) {
        hT[(size_t)bglob * Hh + khid] = hlast;
        cT[(size_t)bglob * Hh + khid] = c;
    }
}

// ---------------- launch ------------------------------------------------------
extern "C" void kernel_launch(void* const* d_in, const int* in_sizes, int n_in,
                              void* d_out, int out_size) {
    const float* x  = (const float*)d_in[0];
    const float* h0 = (const float*)d_in[1];
    const float* c0 = (const float*)d_in[2];
    const float* Wi = (const float*)d_in[3];
    const float* bi = (const float*)d_in[4];
    const float* Wh = (const float*)d_in[5];
    const float* bh = (const float*)d_in[6];

    float* out = (float*)d_out;                       // [B,T,H]
    float* hT  = out + (size_t)Bb * Tt * Hh;          // [B,H]
    float* cT  = hT + (size_t)Bb * Hh;                // [B,H]

    const int lstm_smem = (ROWS * WST + GB * Hh + 4 * 64 * 4) * 4;
    cudaFuncSetAttribute(lstm_kernel, cudaFuncAttributeMaxDynamicSharedMemorySize,
                         lstm_smem);

    permute_kernel<<<RR, 128>>>(Wi, Wh, bi, bh);
    init_kernel<<<32, 256>>>(h0);
    xgemm_kernel<<<dim3((Tt * Bb) / BN, RR / BM), 256>>>(x);
    lstm_kernel<<<NG * GC, 256, lstm_smem>>>(c0, out, hT, cT);
}

// round 12
// speedup vs baseline: 1.0294x; 1.0294x over previous
#include <cuda_runtime.h>
#include <math.h>

#define Bb 16
#define Tt 2048
#define Ii 512
#define Hh 512
#define RR 2048   // 4*H, permuted row order r = 4*j + g
#define NG 4      // independent groups (each owns 4 batches)
#define GC 32     // CTAs per group
#define GB 4      // batches per group
#define ROWS 64   // permuted gate rows per CTA
#define WST 516   // w_s row stride in floats (64x516x4B = 132KB)

// ---------------- persistent device scratch (no runtime allocation) ----------
__device__ float d_WiP[RR * Ii];                 // 4 MB  permuted Wi
__device__ float d_WhP[RR * Hh];                 // 4 MB  permuted Wh
__device__ float d_bsum[RR];                     // bi+bh, permuted
__device__ float d_XG[(size_t)Tt * RR * Bb];     // 268 MB, [t][g][r][b4]
__device__ uint2 d_HX[2][NG * Hh * GB];          // tagged h words (h_bits, tag)

// ---------------- f32x2 helpers ----------------------------------------------
__device__ __forceinline__ unsigned long long ffma2(unsigned long long a,
                                                    unsigned long long b,
                                                    unsigned long long c) {
    unsigned long long d;
    asm("fma.rn.f32x2 %0, %1, %2, %3;" : "=l"(d) : "l"(a), "l"(b), "l"(c));
    return d;
}
__device__ __forceinline__ unsigned long long packdup(float x) {
    unsigned long long r;
    asm("mov.b64 %0, {%1, %1};" : "=l"(r) : "f"(x));
    return r;
}
__device__ __forceinline__ float2 unpk(unsigned long long v) {
    float2 r;
    asm("mov.b64 {%0, %1}, %2;" : "=f"(r.x), "=f"(r.y) : "l"(v));
    return r;
}

// fresh L2 read of 16B (2 tagged words), never hoisted
__device__ __forceinline__ uint4 ldcg4(const uint4* p) {
    uint4 v;
    asm volatile("ld.global.cg.v4.u32 {%0,%1,%2,%3}, [%4];"
                 : "=r"(v.x), "=r"(v.y), "=r"(v.z), "=r"(v.w)
                 : "l"(p) : "memory");
    return v;
}
// publish one tagged word (data+tag atomic in a single 8B store)
__device__ __forceinline__ void st_word(uint2* p, unsigned hbits, unsigned tag) {
    asm volatile("st.global.cg.v2.u32 [%0], {%1, %2};"
                 :: "l"(p), "r"(hbits), "r"(tag) : "memory");
}

__device__ __forceinline__ float sigmoidf_(float x) {
    return 1.f / (1.f + __expf(-x));
}
__device__ __forceinline__ float tanhf_(float x) {
    float e = __expf(2.f * x);
    return (e - 1.f) / (e + 1.f);
}

// ---------------- phase 0a: permute weights, fuse biases ---------------------
__global__ void permute_kernel(const float* __restrict__ Wi,
                               const float* __restrict__ Wh,
                               const float* __restrict__ bi,
                               const float* __restrict__ bh) {
    int rnew = blockIdx.x;            // 0..2047
    int j = rnew >> 2, g = rnew & 3;
    int rold = g * Hh + j;
    const float4* wi4 = (const float4*)(Wi + (size_t)rold * Ii);
    const float4* wh4 = (const float4*)(Wh + (size_t)rold * Hh);
    float4* wiP4 = (float4*)(d_WiP + (size_t)rnew * Ii);
    float4* whP4 = (float4*)(d_WhP + (size_t)rnew * Hh);
    for (int k = threadIdx.x; k < Ii / 4; k += blockDim.x) wiP4[k] = wi4[k];
    for (int k = threadIdx.x; k < Hh / 4; k += blockDim.x) whP4[k] = wh4[k];
    if (threadIdx.x == 0) d_bsum[rnew] = bi[rold] + bh[rold];
}

// ---------------- phase 0b: init tagged h words ------------------------------
__global__ void init_kernel(const float* __restrict__ h0) {
    int idx = blockIdx.x * blockDim.x + threadIdx.x;   // 0..8191
    if (idx < NG * Hh * GB) {
        int g = idx >> 11;
        int k = (idx & 2047) >> 2;
        int b = idx & 3;
        float h = h0[(size_t)(g * GB + b) * Hh + k];
        d_HX[0][idx] = make_uint2(__float_as_uint(h), 0u);       // tag 0 = h(0)
        d_HX[1][idx] = make_uint2(0u, 0xFFFFFFFFu);              // never matches
    }
}

// ---------------- phase 1: xg[t][g][r][b4] = WiP @ x^T + bsum ----------------
#define BM 128
#define BN 128
#define BK 16
#define LDA 132

__global__ __launch_bounds__(256, 2) void xgemm_kernel(const float* __restrict__ x) {
    __shared__ float As[BK * LDA];
    __shared__ float Bs[BK * LDA];
    const int tid = threadIdx.x;
    const int m0 = blockIdx.y * BM;
    const int n0 = blockIdx.x * BN;
    const int tx = tid & 15, ty = tid >> 4;

    unsigned long long acc[8][4];
#pragma unroll
    for (int i = 0; i < 8; i++)
#pragma unroll
        for (int j = 0; j < 4; j++) acc[i][j] = 0ull;

    for (int k0 = 0; k0 < Ii; k0 += BK) {
#pragma unroll
        for (int q = 0; q < 2; q++) {
            int slot = tid + q * 256;
            int row = slot >> 2;
            int kq4 = slot & 3;
            float4 v = *(const float4*)&d_WiP[(size_t)(m0 + row) * Ii + k0 + kq4 * 4];
            As[(kq4 * 4 + 0) * LDA + row] = v.x;
            As[(kq4 * 4 + 1) * LDA + row] = v.y;
            As[(kq4 * 4 + 2) * LDA + row] = v.z;
            As[(kq4 * 4 + 3) * LDA + row] = v.w;
        }
#pragma unroll
        for (int q = 0; q < 2; q++) {
            int slot = tid + q * 256;
            int nn = slot >> 2;
            int kq4 = slot & 3;
            int n = n0 + nn;
            int t = n >> 4, b = n & 15;
            float4 v = *(const float4*)&x[((size_t)b * Tt + t) * Ii + k0 + kq4 * 4];
            Bs[(kq4 * 4 + 0) * LDA + nn] = v.x;
            Bs[(kq4 * 4 + 1) * LDA + nn] = v.y;
            Bs[(kq4 * 4 + 2) * LDA + nn] = v.z;
            Bs[(kq4 * 4 + 3) * LDA + nn] = v.w;
        }
        __syncthreads();
#pragma unroll
        for (int kk = 0; kk < BK; kk++) {
            float a[8];
            *(float4*)&a[0] = *(const float4*)&As[kk * LDA + ty * 8];
            *(float4*)&a[4] = *(const float4*)&As[kk * LDA + ty * 8 + 4];
            ulonglong2 b01 = *(const ulonglong2*)&Bs[kk * LDA + tx * 8];
            ulonglong2 b23 = *(const ulonglong2*)&Bs[kk * LDA + tx * 8 + 4];
#pragma unroll
            for (int i = 0; i < 8; i++) {
                unsigned long long as = packdup(a[i]);
                acc[i][0] = ffma2(as, b01.x, acc[i][0]);
                acc[i][1] = ffma2(as, b01.y, acc[i][1]);
                acc[i][2] = ffma2(as, b23.x, acc[i][2]);
                acc[i][3] = ffma2(as, b23.y, acc[i][3]);
            }
        }
        __syncthreads();
    }
#pragma unroll
    for (int mm = 0; mm < 8; mm++) {
        int r = m0 + ty * 8 + mm;
        float bias = d_bsum[r];
#pragma unroll
        for (int nq = 0; nq < 2; nq++) {
            int n = n0 + tx * 8 + nq * 4;
            int t = n >> 4, b = n & 15;  // b in {0,4,8,12}: 4 batches of group b>>2
            float2 u0 = unpk(acc[mm][nq * 2 + 0]);
            float2 u1 = unpk(acc[mm][nq * 2 + 1]);
            float4 v;
            v.x = u0.x + bias;
            v.y = u0.y + bias;
            v.z = u1.x + bias;
            v.w = u1.y + bias;
            *(float4*)&d_XG[(size_t)t * (RR * Bb) + (size_t)(b >> 2) * (RR * 4) +
                            (size_t)r * 4] = v;
        }
    }
}

// ---------------- phase 2: persistent recurrent kernel -----------------------
// 4 independent groups x 32 CTAs. CTA (g, cl) owns permuted gate rows
// [64cl, 64cl+64) -> hidden [16cl, 16cl+16), batches [4g, 4g+4).
// Exchange via self-validating (h, tag) words: no flags, no fences.
// Tail stage distributed over all 256 threads (1 activation each + shfl gather).
__global__ __launch_bounds__(256, 1) void lstm_kernel(const float* __restrict__ c0,
                                                      float* __restrict__ out,
                                                      float* __restrict__ hT,
                                                      float* __restrict__ cT) {
    extern __shared__ float sm[];
    float* w_s  = sm;                       // 64 x 516         = 132.1 KB
    float* h_s  = w_s + ROWS * WST;         // 512 x 4 [k][b]   = 8 KB
    float* gred = h_s + Hh * GB;            // 4 x 64 x 4       = 4 KB

    const int tid = threadIdx.x;
    const int g  = blockIdx.x >> 5;
    const int cl = blockIdx.x & 31;
    const int kq = tid >> 6;       // k-split 0..3 (128 k each)
    const int rw = tid & 63;       // local gate row 0..63

    // Wh slice -> SMEM (once)
    {
        const float4* src = (const float4*)(d_WhP + (size_t)(cl * ROWS) * Hh);
        for (int i4 = tid; i4 < ROWS * Hh / 4; i4 += 256) {
            int rr = i4 >> 7;
            int k4 = i4 & 127;
            *(float4*)&w_s[rr * WST + k4 * 4] = src[i4];
        }
    }

    // distributed tail mapping: tid = unit*16 + gate*4 + batch
    const int unit = tid >> 4;          // 0..15
    const int gg   = (tid >> 2) & 3;    // gate: 0=i 1=f 2=g 3=o
    const int bb   = tid & 3;           // batch in group
    const int khid  = cl * 16 + unit;
    const int bglob = g * GB + bb;
    float c = 0.f, hlast = 0.f;
    if (gg == 0) c = c0[(size_t)bglob * Hh + khid];
    __syncthreads();

    const float* wrow = w_s + rw * WST + kq * 128;
    const ulonglong2* hpp = (const ulonglong2*)h_s + kq * 128;
    float4* h_s4 = (float4*)h_s;

    // xg prefetch (1 step ahead, registers): kq==0 threads only
    const float4* xg_base0 = (const float4*)(d_XG + (size_t)g * (RR * 4)) +
                             (cl * ROWS + rw);
    float4 xgv_n = make_float4(0.f, 0.f, 0.f, 0.f);
    if (kq == 0)
        xgv_n = __ldcs(xg_base0);                       // xg(t=0)

    for (int t = 0; t < Tt; t++) {
        // consume last step's prefetch; issue load for t+1 immediately
        float4 xgv = xgv_n;
        if (kq == 0 && t + 1 < Tt)
            xgv_n = __ldcs(xg_base0 + (size_t)(t + 1) * (RR * Bb / 4));

        // poll this thread's 64B of tagged words (k = 2*tid, 2*tid+1; all b).
        // Tight spin first (fast path), bounded nanosleep backoff after.
        {
            const uint4* pb = (const uint4*)&d_HX[t & 1][g * 2048] + tid * 4;
            const unsigned tg = (unsigned)t;
            int spins = 0;
            uint4 q0 = ldcg4(pb), q1 = ldcg4(pb + 1),
                  q2 = ldcg4(pb + 2), q3 = ldcg4(pb + 3);
            while ((q0.y != tg) | (q0.w != tg) | (q1.y != tg) | (q1.w != tg) |
                   (q2.y != tg) | (q2.w != tg) | (q3.y != tg) | (q3.w != tg)) {
                if (++spins > 16) __nanosleep(16);
                q0 = ldcg4(pb); q1 = ldcg4(pb + 1);
                q2 = ldcg4(pb + 2); q3 = ldcg4(pb + 3);
            }
            h_s4[2 * tid] =
                make_float4(__uint_as_float(q0.x), __uint_as_float(q0.z),
                            __uint_as_float(q1.x), __uint_as_float(q1.z));
            h_s4[2 * tid + 1] =
                make_float4(__uint_as_float(q2.x), __uint_as_float(q2.z),
                            __uint_as_float(q3.x), __uint_as_float(q3.z));
        }
        __syncthreads();                               // bar1: h_s complete

        // partial gates: row rw, 4 batches, k in [128kq, 128kq+128)
        unsigned long long a0 = 0ull, a1 = 0ull, a2 = 0ull, a3 = 0ull;
#pragma unroll 8
        for (int k4 = 0; k4 < 32; k4++) {
            float4 w4 = *(const float4*)(wrow + 4 * k4);
            ulonglong2 h0v = hpp[4 * k4 + 0];
            ulonglong2 h1v = hpp[4 * k4 + 1];
            ulonglong2 h2v = hpp[4 * k4 + 2];
            ulonglong2 h3v = hpp[4 * k4 + 3];
            unsigned long long w0 = packdup(w4.x);
            unsigned long long w1 = packdup(w4.y);
            unsigned long long w2 = packdup(w4.z);
            unsigned long long w3 = packdup(w4.w);
            a0 = ffma2(w0, h0v.x, a0);  a1 = ffma2(w0, h0v.y, a1);
            a2 = ffma2(w1, h1v.x, a2);  a3 = ffma2(w1, h1v.y, a3);
            a0 = ffma2(w2, h2v.x, a0);  a1 = ffma2(w2, h2v.y, a1);
            a2 = ffma2(w3, h3v.x, a2);  a3 = ffma2(w3, h3v.y, a3);
        }
        {
            float2 p0 = unpk(a0), p1 = unpk(a1), p2 = unpk(a2), p3 = unpk(a3);
            float4 v;
            v.x = p0.x + p2.x;
            v.y = p0.y + p2.y;
            v.z = p1.x + p3.x;
            v.w = p1.y + p3.y;
            if (kq == 0) {
                v.x += xgv.x; v.y += xgv.y; v.z += xgv.z; v.w += xgv.w;
            }
            *(float4*)&gred[(kq * 64 + rw) * 4] = v;
        }
        __syncthreads();                               // bar2: partials ready

        // distributed tail: every thread reduces + activates ITS gate.
        // banks: offset (4*rl + bb) % 32 distinct within each warp -> no conflicts
        {
            int rl = 4 * unit + gg;
            float s = gred[(0 * 64 + rl) * 4 + bb] +
                      gred[(1 * 64 + rl) * 4 + bb] +
                      gred[(2 * 64 + rl) * 4 + bb] +
                      gred[(3 * 64 + rl) * 4 + bb];
            float act = (gg == 2) ? tanhf_(s) : sigmoidf_(s);
            // hand f, g~, o to the gate-0 thread of this (unit, batch)
            float aF = __shfl_down_sync(0xFFFFFFFFu, act, 4);
            float aG = __shfl_down_sync(0xFFFFFFFFu, act, 8);
            float aO = __shfl_down_sync(0xFFFFFFFFu, act, 12);
            if (gg == 0) {
                c = fmaf(aF, c, act * aG);
                float h = aO * tanhf_(c);
                hlast = h;
                // publish: data+tag in one 8B word — no fence needed
                st_word(&d_HX[(t + 1) & 1][g * 2048 + khid * 4 + bb],
                        __float_as_uint(h), (unsigned)(t + 1));
                // background drain; nothing orders after this
                out[((size_t)bglob * Tt + t) * Hh + khid] = h;
            }
        }
        // loop to next poll; gred/h_s single-buffer reuse is safe because the
        // two CTA-wide bars per step order all reads of step t before any
        // writes of step t+1 (any thread passing poll(t+1) has passed bar2(t),
        // and writes for t+1 occur only after bar1(t+1)).
    }

    if (gg == 0) {
        hT[(size_t)bglob * Hh + khid] = hlast;
        cT[(size_t)bglob * Hh + khid] = c;
    }
}

// ---------------- launch ------------------------------------------------------
extern "C" void kernel_launch(void* const* d_in, const int* in_sizes, int n_in,
                              void* d_out, int out_size) {
    const float* x  = (const float*)d_in[0];
    const float* h0 = (const float*)d_in[1];
    const float* c0 = (const float*)d_in[2];
    const float* Wi = (const float*)d_in[3];
    const float* bi = (const float*)d_in[4];
    const float* Wh = (const float*)d_in[5];
    const float* bh = (const float*)d_in[6];

    float* out = (float*)d_out;                       // [B,T,H]
    float* hT  = out + (size_t)Bb * Tt * Hh;          // [B,H]
    float* cT  = hT + (size_t)Bb * Hh;                // [B,H]

    const int lstm_smem = (ROWS * WST + Hh * GB + 4 * 64 * 4) * 4;
    cudaFuncSetAttribute(lstm_kernel, cudaFuncAttributeMaxDynamicSharedMemorySize,
                         lstm_smem);

    permute_kernel<<<RR, 128>>>(Wi, Wh, bi, bh);
    init_kernel<<<32, 256>>>(h0);
    xgemm_kernel<<<dim3((Tt * Bb) / BN, RR / BM), 256>>>(x);
    lstm_kernel<<<NG * GC, 256, lstm_smem>>>(c0, out, hT, cT);
}

// round 15
// speedup vs baseline: 1.1687x; 1.1354x over previous
#include <cuda_runtime.h>
#include <cuda.h>
#include <cstdint>
#include <math.h>

#define Bb 16
#define Tt 2048
#define Ii 512
#define Hh 512
#define RR 2048   // 4*H, permuted row order r = 4*j + g
#define NG 4      // independent groups (each owns 4 batches)
#define GC 32     // CTAs per group
#define GB 4      // batches per group
#define ROWS 64   // permuted gate rows per CTA
#define WST 516   // w_s row stride in floats (64x516x4B = 132KB)

// ---------------- persistent device scratch (no runtime allocation) ----------
__device__ float d_WiP[RR * Ii];                 // 4 MB  permuted Wi
__device__ float d_WhP[RR * Hh];                 // 4 MB  permuted Wh
__device__ float d_bsum[RR];                     // bi+bh, permuted
__device__ float d_XG[(size_t)Tt * RR * Bb];     // 268 MB, [t][g][r][b4]
__device__ uint2 d_HX[2][NG * Hh * GB];          // tagged h words (h_bits, tag)

// ---------------- f32x2 helpers ----------------------------------------------
__device__ __forceinline__ unsigned long long ffma2(unsigned long long a,
                                                    unsigned long long b,
                                                    unsigned long long c) {
    unsigned long long d;
    asm("fma.rn.f32x2 %0, %1, %2, %3;" : "=l"(d) : "l"(a), "l"(b), "l"(c));
    return d;
}
__device__ __forceinline__ unsigned long long packdup(float x) {
    unsigned long long r;
    asm("mov.b64 %0, {%1, %1};" : "=l"(r) : "f"(x));
    return r;
}
__device__ __forceinline__ float2 unpk(unsigned long long v) {
    float2 r;
    asm("mov.b64 {%0, %1}, %2;" : "=f"(r.x), "=f"(r.y) : "l"(v));
    return r;
}

// fresh L2 read of 16B (2 tagged words), never hoisted
__device__ __forceinline__ uint4 ldcg4(const uint4* p) {
    uint4 v;
    asm volatile("ld.global.cg.v4.u32 {%0,%1,%2,%3}, [%4];"
                 : "=r"(v.x), "=r"(v.y), "=r"(v.z), "=r"(v.w)
                 : "l"(p) : "memory");
    return v;
}
// publish one tagged word (data+tag atomic in a single 8B store)
__device__ __forceinline__ void st_word(uint2* p, unsigned hbits, unsigned tag) {
    asm volatile("st.global.cg.v2.u32 [%0], {%1, %2};"
                 :: "l"(p), "r"(hbits), "r"(tag) : "memory");
}

__device__ __forceinline__ float sigmoidf_(float x) {
    return 1.f / (1.f + __expf(-x));
}
__device__ __forceinline__ float tanhf_(float x) {
    float e = __expf(2.f * x);
    return (e - 1.f) / (e + 1.f);
}

// tf32 convert (round-to-nearest-with-ties-away; sm_80+ base PTX)
__device__ __forceinline__ uint32_t f2tf32(float f) {
    uint32_t r;
    asm("cvt.rna.tf32.f32 %0, %1;" : "=r"(r) : "f"(f));
    return r;
}

// ---------------- phase 0a: permute weights, fuse biases ---------------------
__global__ void permute_kernel(const float* __restrict__ Wi,
                               const float* __restrict__ Wh,
                               const float* __restrict__ bi,
                               const float* __restrict__ bh) {
    int rnew = blockIdx.x;            // 0..2047
    int j = rnew >> 2, g = rnew & 3;
    int rold = g * Hh + j;
    const float4* wi4 = (const float4*)(Wi + (size_t)rold * Ii);
    const float4* wh4 = (const float4*)(Wh + (size_t)rold * Hh);
    float4* wiP4 = (float4*)(d_WiP + (size_t)rnew * Ii);
    float4* whP4 = (float4*)(d_WhP + (size_t)rnew * Hh);
    for (int k = threadIdx.x; k < Ii / 4; k += blockDim.x) wiP4[k] = wi4[k];
    for (int k = threadIdx.x; k < Hh / 4; k += blockDim.x) whP4[k] = wh4[k];
    if (threadIdx.x == 0) d_bsum[rnew] = bi[rold] + bh[rold];
}

// ---------------- phase 0b: init tagged h words ------------------------------
__global__ void init_kernel(const float* __restrict__ h0) {
    int idx = blockIdx.x * blockDim.x + threadIdx.x;   // 0..8191
    if (idx < NG * Hh * GB) {
        int g = idx >> 11;
        int k = (idx & 2047) >> 2;
        int b = idx & 3;
        float h = h0[(size_t)(g * GB + b) * Hh + k];
        d_HX[0][idx] = make_uint2(__float_as_uint(h), 0u);       // tag 0 = h(0)
        d_HX[1][idx] = make_uint2(0u, 0xFFFFFFFFu);              // never matches
    }
}

// ---------------- phase 1: tf32 mma.sync GEMM --------------------------------
// xg[t][g][r][b4] = WiP[2048x512] @ X^T + bsum, X[n][k] = x[b][t][k], n=(t,b).
// BM=128, BN=64, K-panels of 32. 8 warps = 4(m) x 2(n), warp tile 32x32.
// mma.sync.m16n8k8 tf32 (base sm_103-legal; runs on the tensor pipe).
#define PSTR 36   // SMEM panel k-stride in words: (36*gid+tg)%32 = 4*gid+tg, conflict-free

__global__ __launch_bounds__(256, 2) void xgemm_tc_kernel(const float* __restrict__ x) {
    __shared__ uint32_t As[128 * PSTR];   // 18.4 KB
    __shared__ uint32_t Bs[64 * PSTR];    //  9.2 KB
    const int tid = threadIdx.x;
    const int wd = tid >> 5, lane = tid & 31;
    const int gid = lane >> 2, tg = lane & 3;
    const int wm = wd >> 1, wn = wd & 1;       // warp grid 4(m) x 2(n)
    const int m0 = blockIdx.y * 128;
    const int n0 = blockIdx.x * 64;
    const int rowb = wm * 32;                  // warp row base in tile
    const int colb = wn * 32;                  // warp col base in tile

    float c[2][4][4];
#pragma unroll
    for (int i = 0; i < 2; i++)
#pragma unroll
        for (int j = 0; j < 4; j++)
#pragma unroll
            for (int q = 0; q < 4; q++) c[i][j][q] = 0.f;

    for (int kb = 0; kb < 16; kb++) {
        // A panel: 128 rows x 32 k, tf32-converted
#pragma unroll
        for (int q = 0; q < 4; q++) {
            int slot = tid + q * 256;          // 0..1023
            int row = slot >> 3;
            int k4  = slot & 7;
            float4 v = *(const float4*)&d_WiP[(size_t)(m0 + row) * Ii + kb * 32 + k4 * 4];
            uint32_t* dst = &As[row * PSTR + k4 * 4];
            dst[0] = f2tf32(v.x); dst[1] = f2tf32(v.y);
            dst[2] = f2tf32(v.z); dst[3] = f2tf32(v.w);
        }
        // B panel: 64 n-rows x 32 k, tf32-converted
#pragma unroll
        for (int q = 0; q < 2; q++) {
            int slot = tid + q * 256;          // 0..511
            int nn = slot >> 3;
            int k4 = slot & 7;
            int n = n0 + nn;
            int t = n >> 4, b = n & 15;
            float4 v = *(const float4*)&x[((size_t)b * Tt + t) * Ii + kb * 32 + k4 * 4];
            uint32_t* dst = &Bs[nn * PSTR + k4 * 4];
            dst[0] = f2tf32(v.x); dst[1] = f2tf32(v.y);
            dst[2] = f2tf32(v.z); dst[3] = f2tf32(v.w);
        }
        __syncthreads();

#pragma unroll
        for (int ks = 0; ks < 4; ks++) {
            int ko = ks * 8;
            uint32_t a[2][4];
#pragma unroll
            for (int mf = 0; mf < 2; mf++) {
                const uint32_t* ap = &As[(rowb + mf * 16 + gid) * PSTR + ko + tg];
                a[mf][0] = ap[0];
                a[mf][1] = ap[8 * PSTR];
                a[mf][2] = ap[4];
                a[mf][3] = ap[8 * PSTR + 4];
            }
#pragma unroll
            for (int nf = 0; nf < 4; nf++) {
                const uint32_t* bp = &Bs[(colb + nf * 8 + gid) * PSTR + ko + tg];
                uint32_t b0 = bp[0], b1 = bp[4];
#pragma unroll
                for (int mf = 0; mf < 2; mf++) {
                    asm("mma.sync.aligned.m16n8k8.row.col.f32.tf32.tf32.f32 "
                        "{%0,%1,%2,%3}, {%4,%5,%6,%7}, {%8,%9}, {%0,%1,%2,%3};"
                        : "+f"(c[mf][nf][0]), "+f"(c[mf][nf][1]),
                          "+f"(c[mf][nf][2]), "+f"(c[mf][nf][3])
                        : "r"(a[mf][0]), "r"(a[mf][1]), "r"(a[mf][2]), "r"(a[mf][3]),
                          "r"(b0), "r"(b1));
                }
            }
        }
        __syncthreads();
    }

    // epilogue: c[mf][nf]: rows rowb+gid(+8), cols colb+nf*8+2tg(+1)
#pragma unroll
    for (int mf = 0; mf < 2; mf++) {
        int r0 = m0 + rowb + mf * 16 + gid;
        float bias0 = d_bsum[r0];
        float bias8 = d_bsum[r0 + 8];
#pragma unroll
        for (int nf = 0; nf < 4; nf++) {
            int n = n0 + colb + nf * 8 + 2 * tg;   // even n; pair (n, n+1) same quad
            int t = n >> 4;
            int bq = (n >> 2) & 3;
            size_t base = (size_t)t * (RR * Bb) + (size_t)bq * (RR * 4) + (n & 3);
            float2 v0 = make_float2(c[mf][nf][0] + bias0, c[mf][nf][1] + bias0);
            float2 v1 = make_float2(c[mf][nf][2] + bias8, c[mf][nf][3] + bias8);
            *(float2*)&d_XG[base + (size_t)r0 * 4] = v0;
            *(float2*)&d_XG[base + (size_t)(r0 + 8) * 4] = v1;
        }
    }
}

// ---------------- phase 2: persistent recurrent kernel (unchanged R12) ------
__global__ __launch_bounds__(256, 1) void lstm_kernel(const float* __restrict__ c0,
                                                      float* __restrict__ out,
                                                      float* __restrict__ hT,
                                                      float* __restrict__ cT) {
    extern __shared__ float sm[];
    float* w_s  = sm;                       // 64 x 516         = 132.1 KB
    float* h_s  = w_s + ROWS * WST;         // 512 x 4 [k][b]   = 8 KB
    float* gred = h_s + Hh * GB;            // 4 x 64 x 4       = 4 KB

    const int tid = threadIdx.x;
    const int g  = blockIdx.x >> 5;
    const int cl = blockIdx.x & 31;
    const int kq = tid >> 6;       // k-split 0..3 (128 k each)
    const int rw = tid & 63;       // local gate row 0..63

    // Wh slice -> SMEM (once)
    {
        const float4* src = (const float4*)(d_WhP + (size_t)(cl * ROWS) * Hh);
        for (int i4 = tid; i4 < ROWS * Hh / 4; i4 += 256) {
            int rr = i4 >> 7;
            int k4 = i4 & 127;
            *(float4*)&w_s[rr * WST + k4 * 4] = src[i4];
        }
    }

    // distributed tail mapping: tid = unit*16 + gate*4 + batch
    const int unit = tid >> 4;          // 0..15
    const int gg   = (tid >> 2) & 3;    // gate: 0=i 1=f 2=g 3=o
    const int bb   = tid & 3;           // batch in group
    const int khid  = cl * 16 + unit;
    const int bglob = g * GB + bb;
    float c = 0.f, hlast = 0.f;
    if (gg == 0) c = c0[(size_t)bglob * Hh + khid];
    __syncthreads();

    const float* wrow = w_s + rw * WST + kq * 128;
    const ulonglong2* hpp = (const ulonglong2*)h_s + kq * 128;
    float4* h_s4 = (float4*)h_s;

    // xg prefetch (1 step ahead, registers): kq==0 threads only
    const float4* xg_base0 = (const float4*)(d_XG + (size_t)g * (RR * 4)) +
                             (cl * ROWS + rw);
    float4 xgv_n = make_float4(0.f, 0.f, 0.f, 0.f);
    if (kq == 0)
        xgv_n = __ldcs(xg_base0);                       // xg(t=0)

    for (int t = 0; t < Tt; t++) {
        float4 xgv = xgv_n;
        if (kq == 0 && t + 1 < Tt)
            xgv_n = __ldcs(xg_base0 + (size_t)(t + 1) * (RR * Bb / 4));

        // poll this thread's 64B of tagged words (k = 2*tid, 2*tid+1; all b).
        {
            const uint4* pb = (const uint4*)&d_HX[t & 1][g * 2048] + tid * 4;
            const unsigned tg = (unsigned)t;
            int spins = 0;
            uint4 q0 = ldcg4(pb), q1 = ldcg4(pb + 1),
                  q2 = ldcg4(pb + 2), q3 = ldcg4(pb + 3);
            while ((q0.y != tg) | (q0.w != tg) | (q1.y != tg) | (q1.w != tg) |
                   (q2.y != tg) | (q2.w != tg) | (q3.y != tg) | (q3.w != tg)) {
                if (++spins > 16) __nanosleep(16);
                q0 = ldcg4(pb); q1 = ldcg4(pb + 1);
                q2 = ldcg4(pb + 2); q3 = ldcg4(pb + 3);
            }
            h_s4[2 * tid] =
                make_float4(__uint_as_float(q0.x), __uint_as_float(q0.z),
                            __uint_as_float(q1.x), __uint_as_float(q1.z));
            h_s4[2 * tid + 1] =
                make_float4(__uint_as_float(q2.x), __uint_as_float(q2.z),
                            __uint_as_float(q3.x), __uint_as_float(q3.z));
        }
        __syncthreads();                               // bar1: h_s complete

        // partial gates: row rw, 4 batches, k in [128kq, 128kq+128)
        unsigned long long a0 = 0ull, a1 = 0ull, a2 = 0ull, a3 = 0ull;
#pragma unroll 8
        for (int k4 = 0; k4 < 32; k4++) {
            float4 w4 = *(const float4*)(wrow + 4 * k4);
            ulonglong2 h0v = hpp[4 * k4 + 0];
            ulonglong2 h1v = hpp[4 * k4 + 1];
            ulonglong2 h2v = hpp[4 * k4 + 2];
            ulonglong2 h3v = hpp[4 * k4 + 3];
            unsigned long long w0 = packdup(w4.x);
            unsigned long long w1 = packdup(w4.y);
            unsigned long long w2 = packdup(w4.z);
            unsigned long long w3 = packdup(w4.w);
            a0 = ffma2(w0, h0v.x, a0);  a1 = ffma2(w0, h0v.y, a1);
            a2 = ffma2(w1, h1v.x, a2);  a3 = ffma2(w1, h1v.y, a3);
            a0 = ffma2(w2, h2v.x, a0);  a1 = ffma2(w2, h2v.y, a1);
            a2 = ffma2(w3, h3v.x, a2);  a3 = ffma2(w3, h3v.y, a3);
        }
        {
            float2 p0 = unpk(a0), p1 = unpk(a1), p2 = unpk(a2), p3 = unpk(a3);
            float4 v;
            v.x = p0.x + p2.x;
            v.y = p0.y + p2.y;
            v.z = p1.x + p3.x;
            v.w = p1.y + p3.y;
            if (kq == 0) {
                v.x += xgv.x; v.y += xgv.y; v.z += xgv.z; v.w += xgv.w;
            }
            *(float4*)&gred[(kq * 64 + rw) * 4] = v;
        }
        __syncthreads();                               // bar2: partials ready

        // distributed tail: every thread reduces + activates ITS gate.
        {
            int rl = 4 * unit + gg;
            float s = gred[(0 * 64 + rl) * 4 + bb] +
                      gred[(1 * 64 + rl) * 4 + bb] +
                      gred[(2 * 64 + rl) * 4 + bb] +
                      gred[(3 * 64 + rl) * 4 + bb];
            float act = (gg == 2) ? tanhf_(s) : sigmoidf_(s);
            float aF = __shfl_down_sync(0xFFFFFFFFu, act, 4);
            float aG = __shfl_down_sync(0xFFFFFFFFu, act, 8);
            float aO = __shfl_down_sync(0xFFFFFFFFu, act, 12);
            if (gg == 0) {
                c = fmaf(aF, c, act * aG);
                float h = aO * tanhf_(c);
                hlast = h;
                st_word(&d_HX[(t + 1) & 1][g * 2048 + khid * 4 + bb],
                        __float_as_uint(h), (unsigned)(t + 1));
                out[((size_t)bglob * Tt + t) * Hh + khid] = h;
            }
        }
    }

    if (gg == 0) {
        hT[(size_t)bglob * Hh + khid] = hlast;
        cT[(size_t)bglob * Hh + khid] = c;
    }
}

// ---------------- launch ------------------------------------------------------
extern "C" void kernel_launch(void* const* d_in, const int* in_sizes, int n_in,
                              void* d_out, int out_size) {
    const float* x  = (const float*)d_in[0];
    const float* h0 = (const float*)d_in[1];
    const float* c0 = (const float*)d_in[2];
    const float* Wi = (const float*)d_in[3];
    const float* bi = (const float*)d_in[4];
    const float* Wh = (const float*)d_in[5];
    const float* bh = (const float*)d_in[6];

    float* out = (float*)d_out;                       // [B,T,H]
    float* hT  = out + (size_t)Bb * Tt * Hh;          // [B,H]
    float* cT  = hT + (size_t)Bb * Hh;                // [B,H]

    const int lstm_smem = (ROWS * WST + Hh * GB + 4 * 64 * 4) * 4;
    cudaFuncSetAttribute(lstm_kernel, cudaFuncAttributeMaxDynamicSharedMemorySize,
                         lstm_smem);

    permute_kernel<<<RR, 128>>>(Wi, Wh, bi, bh);
    init_kernel<<<32, 256>>>(h0);
    xgemm_tc_kernel<<<dim3(512, 16), 256>>>(x);
    lstm_kernel<<<NG * GC, 256, lstm_smem>>>(c0, out, hT, cT);
}

// round 16
// speedup vs baseline: 1.3908x; 1.1900x over previous
#include <cuda_runtime.h>
#include <cuda.h>
#include <cstdint>
#include <math.h>

#define Bb 16
#define Tt 2048
#define Ii 512
#define Hh 512
#define RR 2048   // 4*H, permuted row order r = 4*j + g
#define NG 4      // independent groups (each owns 4 batches)
#define GC 32     // CTAs per group
#define GB 4      // batches per group
#define ROWS 64   // permuted gate rows per CTA
#define WST 516   // w_s row stride in floats (64x516x4B = 132KB)

// ---------------- persistent device scratch (no runtime allocation) ----------
__device__ float d_WiP[RR * Ii];                 // 4 MB  permuted Wi
__device__ float d_WhP[RR * Hh];                 // 4 MB  permuted Wh
__device__ float d_bsum[RR];                     // bi+bh, permuted
__device__ float d_XG[(size_t)Tt * RR * Bb];     // 268 MB, [t][g][r][b4]
__device__ uint2 d_HX[2][NG * Hh * GB];          // tagged h words (h_bits, tag)

// ---------------- f32x2 helpers ----------------------------------------------
__device__ __forceinline__ unsigned long long ffma2(unsigned long long a,
                                                    unsigned long long b,
                                                    unsigned long long c) {
    unsigned long long d;
    asm("fma.rn.f32x2 %0, %1, %2, %3;" : "=l"(d) : "l"(a), "l"(b), "l"(c));
    return d;
}
__device__ __forceinline__ unsigned long long packdup(float x) {
    unsigned long long r;
    asm("mov.b64 %0, {%1, %1};" : "=l"(r) : "f"(x));
    return r;
}
__device__ __forceinline__ float2 unpk(unsigned long long v) {
    float2 r;
    asm("mov.b64 {%0, %1}, %2;" : "=f"(r.x), "=f"(r.y) : "l"(v));
    return r;
}

// fresh L2 read of 16B (2 tagged words), never hoisted
__device__ __forceinline__ uint4 ldcg4(const uint4* p) {
    uint4 v;
    asm volatile("ld.global.cg.v4.u32 {%0,%1,%2,%3}, [%4];"
                 : "=r"(v.x), "=r"(v.y), "=r"(v.z), "=r"(v.w)
                 : "l"(p) : "memory");
    return v;
}
// publish one tagged word (data+tag atomic in a single 8B store)
__device__ __forceinline__ void st_word(uint2* p, unsigned hbits, unsigned tag) {
    asm volatile("st.global.cg.v2.u32 [%0], {%1, %2};"
                 :: "l"(p), "r"(hbits), "r"(tag) : "memory");
}

__device__ __forceinline__ float sigmoidf_(float x) {
    return 1.f / (1.f + __expf(-x));
}
__device__ __forceinline__ float tanhf_(float x) {
    float e = __expf(2.f * x);
    return (e - 1.f) / (e + 1.f);
}

// tf32 convert (round-to-nearest-with-ties-away; sm_80+ base PTX)
__device__ __forceinline__ uint32_t f2tf32(float f) {
    uint32_t r;
    asm("cvt.rna.tf32.f32 %0, %1;" : "=r"(r) : "f"(f));
    return r;
}

// ---------------- phase 0a: permute weights, fuse biases ---------------------
__global__ void permute_kernel(const float* __restrict__ Wi,
                               const float* __restrict__ Wh,
                               const float* __restrict__ bi,
                               const float* __restrict__ bh) {
    int rnew = blockIdx.x;            // 0..2047
    int j = rnew >> 2, g = rnew & 3;
    int rold = g * Hh + j;
    const float4* wi4 = (const float4*)(Wi + (size_t)rold * Ii);
    const float4* wh4 = (const float4*)(Wh + (size_t)rold * Hh);
    float4* wiP4 = (float4*)(d_WiP + (size_t)rnew * Ii);
    float4* whP4 = (float4*)(d_WhP + (size_t)rnew * Hh);
    for (int k = threadIdx.x; k < Ii / 4; k += blockDim.x) wiP4[k] = wi4[k];
    for (int k = threadIdx.x; k < Hh / 4; k += blockDim.x) whP4[k] = wh4[k];
    if (threadIdx.x == 0) d_bsum[rnew] = bi[rold] + bh[rold];
}

// ---------------- phase 0b: init tagged h words ------------------------------
__global__ void init_kernel(const float* __restrict__ h0) {
    int idx = blockIdx.x * blockDim.x + threadIdx.x;   // 0..8191
    if (idx < NG * Hh * GB) {
        int g = idx >> 11;
        int k = (idx & 2047) >> 2;
        int b = idx & 3;
        float h = h0[(size_t)(g * GB + b) * Hh + k];
        d_HX[0][idx] = make_uint2(__float_as_uint(h), 0u);       // tag 0 = h(0)
        d_HX[1][idx] = make_uint2(0u, 0xFFFFFFFFu);              // never matches
    }
}

// ---------------- phase 1: tf32 mma.sync GEMM (unchanged R15) ----------------
#define PSTR 36   // SMEM panel k-stride in words: (36*gid+tg)%32 = 4*gid+tg, conflict-free

__global__ __launch_bounds__(256, 2) void xgemm_tc_kernel(const float* __restrict__ x) {
    __shared__ uint32_t As[128 * PSTR];   // 18.4 KB
    __shared__ uint32_t Bs[64 * PSTR];    //  9.2 KB
    const int tid = threadIdx.x;
    const int wd = tid >> 5, lane = tid & 31;
    const int gid = lane >> 2, tg = lane & 3;
    const int wm = wd >> 1, wn = wd & 1;       // warp grid 4(m) x 2(n)
    const int m0 = blockIdx.y * 128;
    const int n0 = blockIdx.x * 64;
    const int rowb = wm * 32;
    const int colb = wn * 32;

    float c[2][4][4];
#pragma unroll
    for (int i = 0; i < 2; i++)
#pragma unroll
        for (int j = 0; j < 4; j++)
#pragma unroll
            for (int q = 0; q < 4; q++) c[i][j][q] = 0.f;

    for (int kb = 0; kb < 16; kb++) {
#pragma unroll
        for (int q = 0; q < 4; q++) {
            int slot = tid + q * 256;
            int row = slot >> 3;
            int k4  = slot & 7;
            float4 v = *(const float4*)&d_WiP[(size_t)(m0 + row) * Ii + kb * 32 + k4 * 4];
            uint32_t* dst = &As[row * PSTR + k4 * 4];
            dst[0] = f2tf32(v.x); dst[1] = f2tf32(v.y);
            dst[2] = f2tf32(v.z); dst[3] = f2tf32(v.w);
        }
#pragma unroll
        for (int q = 0; q < 2; q++) {
            int slot = tid + q * 256;
            int nn = slot >> 3;
            int k4 = slot & 7;
            int n = n0 + nn;
            int t = n >> 4, b = n & 15;
            float4 v = *(const float4*)&x[((size_t)b * Tt + t) * Ii + kb * 32 + k4 * 4];
            uint32_t* dst = &Bs[nn * PSTR + k4 * 4];
            dst[0] = f2tf32(v.x); dst[1] = f2tf32(v.y);
            dst[2] = f2tf32(v.z); dst[3] = f2tf32(v.w);
        }
        __syncthreads();

#pragma unroll
        for (int ks = 0; ks < 4; ks++) {
            int ko = ks * 8;
            uint32_t a[2][4];
#pragma unroll
            for (int mf = 0; mf < 2; mf++) {
                const uint32_t* ap = &As[(rowb + mf * 16 + gid) * PSTR + ko + tg];
                a[mf][0] = ap[0];
                a[mf][1] = ap[8 * PSTR];
                a[mf][2] = ap[4];
                a[mf][3] = ap[8 * PSTR + 4];
            }
#pragma unroll
            for (int nf = 0; nf < 4; nf++) {
                const uint32_t* bp = &Bs[(colb + nf * 8 + gid) * PSTR + ko + tg];
                uint32_t b0 = bp[0], b1 = bp[4];
#pragma unroll
                for (int mf = 0; mf < 2; mf++) {
                    asm("mma.sync.aligned.m16n8k8.row.col.f32.tf32.tf32.f32 "
                        "{%0,%1,%2,%3}, {%4,%5,%6,%7}, {%8,%9}, {%0,%1,%2,%3};"
                        : "+f"(c[mf][nf][0]), "+f"(c[mf][nf][1]),
                          "+f"(c[mf][nf][2]), "+f"(c[mf][nf][3])
                        : "r"(a[mf][0]), "r"(a[mf][1]), "r"(a[mf][2]), "r"(a[mf][3]),
                          "r"(b0), "r"(b1));
                }
            }
        }
        __syncthreads();
    }

#pragma unroll
    for (int mf = 0; mf < 2; mf++) {
        int r0 = m0 + rowb + mf * 16 + gid;
        float bias0 = d_bsum[r0];
        float bias8 = d_bsum[r0 + 8];
#pragma unroll
        for (int nf = 0; nf < 4; nf++) {
            int n = n0 + colb + nf * 8 + 2 * tg;
            int t = n >> 4;
            int bq = (n >> 2) & 3;
            size_t base = (size_t)t * (RR * Bb) + (size_t)bq * (RR * 4) + (n & 3);
            float2 v0 = make_float2(c[mf][nf][0] + bias0, c[mf][nf][1] + bias0);
            float2 v1 = make_float2(c[mf][nf][2] + bias8, c[mf][nf][3] + bias8);
            *(float2*)&d_XG[base + (size_t)r0 * 4] = v0;
            *(float2*)&d_XG[base + (size_t)(r0 + 8) * 4] = v1;
        }
    }
}

// ---------------- phase 2: persistent recurrent kernel -----------------------
// 4 groups x 32 CTAs, now 512 threads: 8-way k-split, thread tid polls k=tid
// (exactly its own chunk's producers). bar1 replaced by 8 parallel 64-thread
// pair barriers; one full __syncthreads before the distributed tail.
__global__ __launch_bounds__(512, 1) void lstm_kernel(const float* __restrict__ c0,
                                                      float* __restrict__ out,
                                                      float* __restrict__ hT,
                                                      float* __restrict__ cT) {
    extern __shared__ float sm[];
    float* w_s  = sm;                       // 64 x 516         = 132.1 KB
    float* h_s  = w_s + ROWS * WST;         // 512 x 4 [k][b]   = 8 KB
    float* gred = h_s + Hh * GB;            // 8 x 64 x 4       = 8 KB

    const int tid = threadIdx.x;
    const int g  = blockIdx.x >> 5;
    const int cl = blockIdx.x & 31;
    const int kq = tid >> 6;       // k-split 0..7 (64 k each)
    const int rw = tid & 63;       // local gate row 0..63

    // Wh slice -> SMEM (once)
    {
        const float4* src = (const float4*)(d_WhP + (size_t)(cl * ROWS) * Hh);
        for (int i4 = tid; i4 < ROWS * Hh / 4; i4 += 512) {
            int rr = i4 >> 7;
            int k4 = i4 & 127;
            *(float4*)&w_s[rr * WST + k4 * 4] = src[i4];
        }
    }

    // distributed tail mapping (tid < 256): tid = unit*16 + gate*4 + batch
    const int unit = tid >> 4;          // 0..15 (valid when tid < 256)
    const int gg   = (tid >> 2) & 3;    // gate: 0=i 1=f 2=g 3=o
    const int bb   = tid & 3;           // batch in group
    const int khid  = cl * 16 + unit;
    const int bglob = g * GB + bb;
    float c = 0.f, hlast = 0.f;
    if (tid < 256 && gg == 0) c = c0[(size_t)bglob * Hh + khid];
    __syncthreads();

    const float* wrow = w_s + rw * WST + kq * 64;
    const ulonglong2* hpp = (const ulonglong2*)h_s + kq * 64;
    float4* h_s4 = (float4*)h_s;

    // xg prefetch (1 step ahead, registers): kq==0 threads only
    const float4* xg_base0 = (const float4*)(d_XG + (size_t)g * (RR * 4)) +
                             (cl * ROWS + rw);
    float4 xgv_n = make_float4(0.f, 0.f, 0.f, 0.f);
    if (kq == 0)
        xgv_n = __ldcs(xg_base0);                       // xg(t=0)

    for (int t = 0; t < Tt; t++) {
        float4 xgv = xgv_n;
        if (kq == 0 && t + 1 < Tt)
            xgv_n = __ldcs(xg_base0 + (size_t)(t + 1) * (RR * Bb / 4));

        // poll k = tid's 32B of tagged words (4 (h,tag) pairs, all batches).
        // Producer of k=tid is CTA tid/16 -> within this pair's chunk.
        {
            const uint4* pb = (const uint4*)&d_HX[t & 1][g * 2048] + tid * 2;
            const unsigned tg = (unsigned)t;
            int spins = 0;
            uint4 q0 = ldcg4(pb), q1 = ldcg4(pb + 1);
            while ((q0.y != tg) | (q0.w != tg) | (q1.y != tg) | (q1.w != tg)) {
                if (++spins > 16) __nanosleep(16);
                q0 = ldcg4(pb); q1 = ldcg4(pb + 1);
            }
            h_s4[tid] =
                make_float4(__uint_as_float(q0.x), __uint_as_float(q0.z),
                            __uint_as_float(q1.x), __uint_as_float(q1.z));
        }
        // pair barrier: this chunk's 64 writers == its 64 readers
        asm volatile("bar.sync %0, 64;" :: "r"(1 + kq) : "memory");

        // partial gates: row rw, 4 batches, k in [64kq, 64kq+64)
        unsigned long long a0 = 0ull, a1 = 0ull, a2 = 0ull, a3 = 0ull;
#pragma unroll
        for (int k4 = 0; k4 < 16; k4++) {
            float4 w4 = *(const float4*)(wrow + 4 * k4);
            ulonglong2 h0v = hpp[4 * k4 + 0];
            ulonglong2 h1v = hpp[4 * k4 + 1];
            ulonglong2 h2v = hpp[4 * k4 + 2];
            ulonglong2 h3v = hpp[4 * k4 + 3];
            unsigned long long w0 = packdup(w4.x);
            unsigned long long w1 = packdup(w4.y);
            unsigned long long w2 = packdup(w4.z);
            unsigned long long w3 = packdup(w4.w);
            a0 = ffma2(w0, h0v.x, a0);  a1 = ffma2(w0, h0v.y, a1);
            a2 = ffma2(w1, h1v.x, a2);  a3 = ffma2(w1, h1v.y, a3);
            a0 = ffma2(w2, h2v.x, a0);  a1 = ffma2(w2, h2v.y, a1);
            a2 = ffma2(w3, h3v.x, a2);  a3 = ffma2(w3, h3v.y, a3);
        }
        {
            float2 p0 = unpk(a0), p1 = unpk(a1), p2 = unpk(a2), p3 = unpk(a3);
            float4 v;
            v.x = p0.x + p2.x;
            v.y = p0.y + p2.y;
            v.z = p1.x + p3.x;
            v.w = p1.y + p3.y;
            if (kq == 0) {
                v.x += xgv.x; v.y += xgv.y; v.z += xgv.z; v.w += xgv.w;
            }
            *(float4*)&gred[(kq * 64 + rw) * 4] = v;
        }
        __syncthreads();                               // bar2: partials ready

        // distributed tail (tid < 256): reduce 8 partials + activate ONE gate.
        // gred idx = kq*256 + tid -> bank tid%32: conflict-free.
        if (tid < 256) {
            int rl = 4 * unit + gg;
            float s = 0.f;
#pragma unroll
            for (int q = 0; q < 8; q++)
                s += gred[q * 256 + rl * 4 + bb];
            float act = (gg == 2) ? tanhf_(s) : sigmoidf_(s);
            float aF = __shfl_down_sync(0xFFFFFFFFu, act, 4);
            float aG = __shfl_down_sync(0xFFFFFFFFu, act, 8);
            float aO = __shfl_down_sync(0xFFFFFFFFu, act, 12);
            if (gg == 0) {
                c = fmaf(aF, c, act * aG);
                float h = aO * tanhf_(c);
                hlast = h;
                st_word(&d_HX[(t + 1) & 1][g * 2048 + khid * 4 + bb],
                        __float_as_uint(h), (unsigned)(t + 1));
                out[((size_t)bglob * Tt + t) * Hh + khid] = h;
            }
        }
        // reuse safety: passing poll(t+1) implies our own tail published t+1,
        // which implies every thread passed bar2(t) (full CTA) and the tail
        // finished reading gred(t) — so chunk-local h_s/gred rewrites are safe.
    }

    if (tid < 256 && gg == 0) {
        hT[(size_t)bglob * Hh + khid] = hlast;
        cT[(size_t)bglob * Hh + khid] = c;
    }
}

// ---------------- launch ------------------------------------------------------
extern "C" void kernel_launch(void* const* d_in, const int* in_sizes, int n_in,
                              void* d_out, int out_size) {
    const float* x  = (const float*)d_in[0];
    const float* h0 = (const float*)d_in[1];
    const float* c0 = (const float*)d_in[2];
    const float* Wi = (const float*)d_in[3];
    const float* bi = (const float*)d_in[4];
    const float* Wh = (const float*)d_in[5];
    const float* bh = (const float*)d_in[6];

    float* out = (float*)d_out;                       // [B,T,H]
    float* hT  = out + (size_t)Bb * Tt * Hh;          // [B,H]
    float* cT  = hT + (size_t)Bb * Hh;                // [B,H]

    const int lstm_smem = (ROWS * WST + Hh * GB + 8 * 64 * 4) * 4;
    cudaFuncSetAttribute(lstm_kernel, cudaFuncAttributeMaxDynamicSharedMemorySize,
                         lstm_smem);

    permute_kernel<<<RR, 128>>>(Wi, Wh, bi, bh);
    init_kernel<<<32, 256>>>(h0);
    xgemm_tc_kernel<<<dim3(512, 16), 256>>>(x);
    lstm_kernel<<<NG * GC, 512, lstm_smem>>>(c0, out, hT, cT);
}